// round 8
// baseline (speedup 1.0000x reference)
#include <cuda_runtime.h>
#include <cstdint>

// Problem constants (fixed by the reference)
#define B   32
#define D   576
#define L   196
#define CC  10
#define K   256
#define M   (CC * K)          // 2560
#define NWP 8                 // packed words per (b,d) row
#define MAXSEL 64             // max selected literals per clause (mean ~11.5)

// Bit layout (fixed permutation, consistent between pack & clause phases):
//   words 0..3 : element l = 4*j + k     (l < 128)     -> word k,   bit j (0..31)
//   words 4..7 : element l = 128+4*j+k   (128..195)    -> word 4+k, bit j (0..16)

// Persistent launch shape: single co-resident wave.
#define NBLK    592                       // 4 x 148 (GB300 has 152 SMs -> resident)
#define NTHR    256
#define NWARPS  (NBLK * 8)                // 4736

#define ROWS_PER_UNIT 4
#define PACK_UNITS  ((B * D) / ROWS_PER_UNIT)   // 4608
#define LIST_UNITS  M                           // 2560
#define PREP_UNITS  (PACK_UNITS + LIST_UNITS)   // 7168
#define CLAUSE_UNITS (M * (B / 4))              // 20480  (m, b0-group)
#define LOGITS_UNITS (B * CC)                   // 320

// ---------------- scratch (no allocation allowed) ----------------
__device__ uint32_t      g_litbits[D * B * NWP];  // 576 KB (L2-resident)
__device__ int16_t       g_idx[M * MAXSEL];       // per-clause selected d (padded)
__device__ int           g_cnt[M];                // per-clause count (mult of 4)
__device__ unsigned char g_or[B * M];             // clause_or bits for logits
__device__ int           g_mask_dtype;            // 0=uint8, 1=float32, 2=int32
__device__ int           g_dt_ready;              // detect-done flag
__device__ int           c_prep, c_clause, c_logits;  // barrier counters (reset at end)

__device__ __forceinline__ void spin_ge(volatile int* p, int target) {
    while (*p < target) { __nanosleep(64); }
}

// ==================== the single fused persistent kernel ====================
__global__ void __launch_bounds__(NTHR, 4)
fused_kernel(const float* __restrict__ lit,
             const void*  __restrict__ mask,
             const float* __restrict__ alpha,
             float* __restrict__ out_map,
             float* __restrict__ out_or,
             float* __restrict__ out_logits) {
    int tid  = threadIdx.x;
    int lane = tid & 31;
    int wblk = tid >> 5;
    int gw   = blockIdx.x * 8 + wblk;        // global warp id, 0..4735

    // ---------- phase 0: dtype detect (block 0 only; others proceed to pack) ----------
    if (blockIdx.x == 0) {
        // mask values are 0/1 booleans; as 32-bit words:
        //   float32 -> {0, 0x3F800000}; int32 -> {0,1}; uint8 -> packed 0/1 bytes
        __shared__ int s_float, s_multi;
        if (tid == 0) { s_float = 0; s_multi = 0; }
        __syncthreads();
        const uint32_t* w = (const uint32_t*)mask;
        for (int i = tid; i < 4096; i += NTHR) {
            uint32_t v = w[i];
            if (v == 0x3F800000u) s_float = 1;            // benign race
            else if (v != 0u && v != 1u) s_multi = 1;
        }
        __syncthreads();
        if (tid == 0) {
            g_mask_dtype = s_float ? 1 : (s_multi ? 0 : 2);
            __threadfence();
            *(volatile int*)&g_dt_ready = 1;
        }
    }

    // ---------- phase 1: prep units (pack first in stripe order, then list) ----------
    int dt = -1;
    for (int u = gw; u < PREP_UNITS; u += NWARPS) {
        if (u < PACK_UNITS) {
            // ---- pack unit: 4 consecutive (b,d) rows, all loads issued upfront
            int row0 = u * ROWS_PER_UNIT;
            int b = row0 / D;
            int d = row0 - b * D;
            float4 ga[ROWS_PER_UNIT], gb[ROWS_PER_UNIT];
#pragma unroll
            for (int r = 0; r < ROWS_PER_UNIT; ++r) {
                const float4* rr = (const float4*)(lit + (size_t)(row0 + r) * L);
                ga[r] = rr[lane];                                   // l = 4*lane..+3
                gb[r] = (lane < 17) ? rr[32 + lane]                 // l = 128+4*lane..+3
                                    : make_float4(0.f, 0.f, 0.f, 0.f);
            }
#pragma unroll
            for (int r = 0; r < ROWS_PER_UNIT; ++r) {
                unsigned w0 = __ballot_sync(0xFFFFFFFFu, ga[r].x > 0.5f);
                unsigned w1 = __ballot_sync(0xFFFFFFFFu, ga[r].y > 0.5f);
                unsigned w2 = __ballot_sync(0xFFFFFFFFu, ga[r].z > 0.5f);
                unsigned w3 = __ballot_sync(0xFFFFFFFFu, ga[r].w > 0.5f);
                unsigned w4 = __ballot_sync(0xFFFFFFFFu, gb[r].x > 0.5f);
                unsigned w5 = __ballot_sync(0xFFFFFFFFu, gb[r].y > 0.5f);
                unsigned w6 = __ballot_sync(0xFFFFFFFFu, gb[r].z > 0.5f);
                unsigned w7 = __ballot_sync(0xFFFFFFFFu, gb[r].w > 0.5f);
                unsigned out = w0;
                if (lane == 1) out = w1;
                if (lane == 2) out = w2;
                if (lane == 3) out = w3;
                if (lane == 4) out = w4;
                if (lane == 5) out = w5;
                if (lane == 6) out = w6;
                if (lane == 7) out = w7;
                if (lane < NWP) g_litbits[d * (B * NWP) + b * NWP + lane] = out;
                if (++d == D) { d = 0; ++b; }
            }
        } else {
            // ---- list unit: one clause row, MLP-batched, unified dtype handling.
            // Element index d = c*128 + 4*lane + k for chunk c, component k.
            int m = u - PACK_UNITS;
            if (dt < 0) {                          // first list unit: get dtype
                spin_ge(&g_dt_ready, 1);
                __threadfence();
                dt = g_mask_dtype;
            }
            uint32_t vk[5][4];
            if (dt != 0) {
                // 4-byte elements: chunk c = uint4 index c*32+lane
                const uint4* row4 = (const uint4*)((const uint32_t*)mask + (size_t)m * D);
                uint4 wv[5];
#pragma unroll
                for (int c = 0; c < 4; ++c) wv[c] = row4[c * 32 + lane];
                wv[4] = (lane < 16) ? row4[128 + lane] : make_uint4(0, 0, 0, 0);
#pragma unroll
                for (int c = 0; c < 5; ++c) {
                    vk[c][0] = wv[c].x; vk[c][1] = wv[c].y;
                    vk[c][2] = wv[c].z; vk[c][3] = wv[c].w;
                }
            } else {
                // 1-byte elements: chunk c = uint32 word c*32+lane (4 bytes -> 4 d's)
                const uint32_t* row32 = (const uint32_t*)((const unsigned char*)mask + (size_t)m * D);
                uint32_t wv[5];
#pragma unroll
                for (int c = 0; c < 4; ++c) wv[c] = row32[c * 32 + lane];
                wv[4] = (lane < 16) ? row32[128 + lane] : 0u;
#pragma unroll
                for (int c = 0; c < 5; ++c) {
                    vk[c][0] = wv[c] & 0xFFu;         vk[c][1] = (wv[c] >> 8) & 0xFFu;
                    vk[c][2] = (wv[c] >> 16) & 0xFFu; vk[c][3] = (wv[c] >> 24) & 0xFFu;
                }
            }
            int cnt = 0, firstd = -1;
#pragma unroll
            for (int c = 0; c < 5; ++c)
#pragma unroll
                for (int k = 0; k < 4; ++k) {
                    bool sel = (vk[c][k] != 0u);
                    unsigned bal = __ballot_sync(0xFFFFFFFFu, sel);
                    if (firstd < 0 && bal) firstd = c * 128 + 4 * (__ffs(bal) - 1) + k;
                    int pos = cnt + __popc(bal & ((1u << lane) - 1u));
                    if (sel && pos < MAXSEL)
                        g_idx[m * MAXSEL + pos] = (int16_t)(c * 128 + 4 * lane + k);
                    cnt += __popc(bal);
                }
            if (cnt > MAXSEL) cnt = MAXSEL;
            int cnt4 = (cnt + 3) & ~3;
            if (lane < cnt4 - cnt) g_idx[m * MAXSEL + cnt + lane] = (int16_t)firstd;
            if (lane == 0) g_cnt[m] = cnt4;
        }
    }

    // ---------- grid barrier 1 (all blocks co-resident -> safe) ----------
    __syncthreads();
    if (tid == 0) {
        __threadfence();
        atomicAdd(&c_prep, 1);
        spin_ge(&c_prep, NBLK);
        __threadfence();
    }
    __syncthreads();

    // ---------- phase 2: clause units ----------
    for (int u = gw; u < CLAUSE_UNITS; u += NWARPS) {
        int m  = u >> 3;
        int b0 = (u & 7) << 2;

        int bq = lane >> 3;                               // 0..3
        int w  = lane & 7;                                // 0..7
        int cnt4 = g_cnt[m];
        const int16_t* idxp = g_idx + m * MAXSEL;

        unsigned acc = 0xFFFFFFFFu;
        {
            const uint32_t* base = g_litbits + (b0 + bq) * NWP + w;
            for (int i = 0; i < cnt4; i += 4) {
                uint64_t q = *(const uint64_t*)(idxp + i);
                int d0 = (int)(q & 0xFFFFu);
                int d1 = (int)((q >> 16) & 0xFFFFu);
                int d2 = (int)((q >> 32) & 0xFFFFu);
                int d3 = (int)((q >> 48) & 0xFFFFu);
                unsigned a0 = base[d0 * (B * NWP)];
                unsigned a1 = base[d1 * (B * NWP)];
                unsigned a2 = base[d2 * (B * NWP)];
                unsigned a3 = base[d3 * (B * NWP)];
                acc &= (a0 & a1) & (a2 & a3);
            }
            if (w >= 4) acc &= 0x1FFFFu;                  // group-B words: 17 valid bits
        }

#pragma unroll
        for (int q = 0; q < 4; ++q) {
            uint4* row = (uint4*)(out_map + ((size_t)(b0 + q) * M + m) * L);
            unsigned w0 = __shfl_sync(0xFFFFFFFFu, acc, q * 8 + 0);
            unsigned w1 = __shfl_sync(0xFFFFFFFFu, acc, q * 8 + 1);
            unsigned w2 = __shfl_sync(0xFFFFFFFFu, acc, q * 8 + 2);
            unsigned w3 = __shfl_sync(0xFFFFFFFFu, acc, q * 8 + 3);
            uint4 v;
            v.x = ((w0 >> lane) & 1u) * 0x3F800000u;
            v.y = ((w1 >> lane) & 1u) * 0x3F800000u;
            v.z = ((w2 >> lane) & 1u) * 0x3F800000u;
            v.w = ((w3 >> lane) & 1u) * 0x3F800000u;
            row[lane] = v;
            unsigned w4 = __shfl_sync(0xFFFFFFFFu, acc, q * 8 + 4);
            unsigned w5 = __shfl_sync(0xFFFFFFFFu, acc, q * 8 + 5);
            unsigned w6 = __shfl_sync(0xFFFFFFFFu, acc, q * 8 + 6);
            unsigned w7 = __shfl_sync(0xFFFFFFFFu, acc, q * 8 + 7);
            if (lane < 17) {
                uint4 uu;
                uu.x = ((w4 >> lane) & 1u) * 0x3F800000u;
                uu.y = ((w5 >> lane) & 1u) * 0x3F800000u;
                uu.z = ((w6 >> lane) & 1u) * 0x3F800000u;
                uu.w = ((w7 >> lane) & 1u) * 0x3F800000u;
                row[32 + lane] = uu;
            }
        }

        bool nz = (acc != 0u);
        unsigned bal = __ballot_sync(0xFFFFFFFFu, nz);
        if (lane < 4) {
            unsigned any = (bal >> (lane * 8)) & 0xFFu;
            int gi = (b0 + lane) * M + m;
            out_or[gi] = any ? 1.0f : 0.0f;
            g_or[gi]   = any ? 1 : 0;
        }
    }

    // ---------- grid barrier 2 ----------
    __syncthreads();
    if (tid == 0) {
        __threadfence();
        atomicAdd(&c_clause, 1);
        spin_ge(&c_clause, NBLK);
        __threadfence();
    }
    __syncthreads();

    // ---------- phase 3: logits (first 320 warps) ----------
    if (gw < LOGITS_UNITS) {
        int b = gw / CC;
        int c = gw - b * CC;
        float s = 0.0f;
        for (int k = lane; k < K; k += 32) {
            int idx = c * K + k;
            float z = g_or[b * M + idx] ? 1.0f : 0.0f;
            float sg = (k < (K / 2)) ? 1.0f : -1.0f;
            s += z * alpha[idx] * sg;
        }
#pragma unroll
        for (int off = 16; off; off >>= 1) s += __shfl_xor_sync(0xFFFFFFFFu, s, off);
        if (lane == 0) {
            out_logits[gw] = s;
            __threadfence();
            atomicAdd(&c_logits, 1);
        }
    }

    // ---------- epilogue: block 0 thread 0 resets control state for next replay ----------
    // Safe: nothing waits on post-reset values this replay; next replay is
    // stream-ordered after this kernel fully completes.
    if (blockIdx.x == 0 && tid == 0) {
        spin_ge(&c_logits, LOGITS_UNITS);
        c_prep = 0; c_clause = 0; c_logits = 0; g_dt_ready = 0;
        __threadfence();
    }
}

// ---------------- launch ----------------
extern "C" void kernel_launch(void* const* d_in, const int* in_sizes, int n_in,
                              void* d_out, int out_size) {
    const void* p_lit   = d_in[0];
    const void* p_mask  = d_in[1];
    const void* p_alpha = d_in[2];
    for (int i = 0; i < n_in; ++i) {
        if (in_sizes[i] == B * D * L)  p_lit   = d_in[i];
        else if (in_sizes[i] == M * D) p_mask  = d_in[i];
        else if (in_sizes[i] == M)     p_alpha = d_in[i];
    }
    float* out_map    = (float*)d_out;                 // [B,M,L]
    float* out_or     = out_map + (size_t)B * M * L;   // [B,M]
    float* out_logits = out_or + (size_t)B * M;        // [B,CC]

    fused_kernel<<<NBLK, NTHR>>>((const float*)p_lit, p_mask, (const float*)p_alpha,
                                 out_map, out_or, out_logits);
}

// round 10
// speedup vs baseline: 1.4556x; 1.4556x over previous
#include <cuda_runtime.h>
#include <cstdint>

// Problem constants (fixed by the reference)
#define B   32
#define D   576
#define L   196
#define CC  10
#define K   256
#define M   (CC * K)          // 2560
#define NWP 8                 // packed words per (b,d) row
#define MAXSEL 64             // max selected literals per clause (mean ~11.5)

// Bit layout (fixed permutation, consistent between pack & clause kernels):
//   words 0..3 : element l = 4*j + k     (l < 128)  -> word k,   bit j (0..31)
//   words 4..7 : element l = 128+4*j+k   (128..195) -> word 4+k, bit j (0..16)

#define ROWS_PER_UNIT 2
#define LIST_BLOCKS   (M / 8)                                  // 320
#define PACK_WARPS    ((B * D) / ROWS_PER_UNIT)                // 9216
#define PACK_BLOCKS   (PACK_WARPS / 8)                         // 1152
#define PREP_BLOCKS   (1 + LIST_BLOCKS + PACK_BLOCKS)          // 1473

// ---------------- scratch (no allocation allowed) ----------------
// litbits word index = d*(B*NWP) + b*NWP + w  -> clause gathers hit ONE 128B line
__device__ uint32_t      g_litbits[D * B * NWP];  // 576 KB (L2-resident)
__device__ int16_t       g_idx[M * MAXSEL];       // per-clause selected d (padded)
__device__ int           g_cnt[M];                // per-clause count (mult of 4)
__device__ int           g_mask_dtype;            // 0=uint8, 1=float32, 2=int32
__device__ volatile int  g_dt_ready;              // detect-done flag

// g_dt_ready across graph replays: detect rewrites g_mask_dtype (identical
// value, identical inputs) before setting the flag; a stale 1 from the prior
// replay lets list warps read either replay's dtype -- identical either way.

// ---------------- kernel 1: fused prep (detect | list | pack) ----------------
__global__ void __launch_bounds__(256) prep_kernel(const float* __restrict__ lit,
                                                   const void*  __restrict__ mask,
                                                   float* __restrict__ out_logits) {
    int lane = threadIdx.x & 31;
    int wblk = threadIdx.x >> 5;

    if (blockIdx.x == 0) {
        // ---- zero ALL B*CC logits (320 > blockDim: must stride!) + detect.
        for (int i = threadIdx.x; i < B * CC; i += blockDim.x)
            out_logits[i] = 0.0f;
        // Mask values are 0/1 booleans; as 32-bit words:
        //   float32 -> {0, 0x3F800000}; int32 -> {0,1}; uint8 -> packed bytes
        __shared__ int s_float, s_multi;
        if (threadIdx.x == 0) { s_float = 0; s_multi = 0; }
        __syncthreads();
        const uint32_t* w = (const uint32_t*)mask;
        for (int i = threadIdx.x; i < 4096; i += blockDim.x) {
            uint32_t v = w[i];
            if (v == 0x3F800000u) s_float = 1;            // benign race
            else if (v != 0u && v != 1u) s_multi = 1;
        }
        __syncthreads();
        if (threadIdx.x == 0) {
            g_mask_dtype = s_float ? 1 : (s_multi ? 0 : 2);
            __threadfence();
            g_dt_ready = 1;
        }
        return;
    }

    if (blockIdx.x <= LIST_BLOCKS) {
        // ---- list: warp per clause. Spin on dtype (block 0 is wave-1
        // resident -> no deadlock; value input-deterministic across replays),
        // then MLP-batched row load + ballot/popc compaction.
        int m = (blockIdx.x - 1) * 8 + wblk;
        while (g_dt_ready == 0) { __nanosleep(32); }
        __threadfence();
        int dt = g_mask_dtype;

        uint32_t vk[5][4];
        if (dt != 0) {
            // 4-byte elements: element d = c*128 + 4*lane + k
            const uint4* row4 = (const uint4*)((const uint32_t*)mask + (size_t)m * D);
            uint4 wv[5];
#pragma unroll
            for (int c = 0; c < 4; ++c) wv[c] = row4[c * 32 + lane];
            wv[4] = (lane < 16) ? row4[128 + lane] : make_uint4(0, 0, 0, 0);
#pragma unroll
            for (int c = 0; c < 5; ++c) {
                vk[c][0] = wv[c].x; vk[c][1] = wv[c].y;
                vk[c][2] = wv[c].z; vk[c][3] = wv[c].w;
            }
        } else {
            // 1-byte elements: word c*32+lane holds elements d = c*128+4*lane+k
            const uint32_t* row32 = (const uint32_t*)((const unsigned char*)mask + (size_t)m * D);
            uint32_t wv[5];
#pragma unroll
            for (int c = 0; c < 4; ++c) wv[c] = row32[c * 32 + lane];
            wv[4] = (lane < 16) ? row32[128 + lane] : 0u;
#pragma unroll
            for (int c = 0; c < 5; ++c) {
                vk[c][0] = wv[c] & 0xFFu;         vk[c][1] = (wv[c] >> 8) & 0xFFu;
                vk[c][2] = (wv[c] >> 16) & 0xFFu; vk[c][3] = (wv[c] >> 24) & 0xFFu;
            }
        }
        int cnt = 0, firstd = -1;
#pragma unroll
        for (int c = 0; c < 5; ++c)
#pragma unroll
            for (int k = 0; k < 4; ++k) {
                bool sel = (vk[c][k] != 0u);
                unsigned bal = __ballot_sync(0xFFFFFFFFu, sel);
                if (firstd < 0 && bal) firstd = c * 128 + 4 * (__ffs(bal) - 1) + k;
                int pos = cnt + __popc(bal & ((1u << lane) - 1u));
                if (sel && pos < MAXSEL)
                    g_idx[m * MAXSEL + pos] = (int16_t)(c * 128 + 4 * lane + k);
                cnt += __popc(bal);
            }
        if (cnt > MAXSEL) cnt = MAXSEL;
        int cnt4 = (cnt + 3) & ~3;
        if (lane < cnt4 - cnt) g_idx[m * MAXSEL + cnt + lane] = (int16_t)firstd;
        if (lane == 0) g_cnt[m] = cnt4;
        return;
    }

    // ---- pack: warp handles 2 consecutive (b,d) rows; 4 x LDG.128 upfront,
    // then register-only ballots. Store layout [d][b][8] words.
    int pw   = (blockIdx.x - 1 - LIST_BLOCKS) * 8 + wblk;     // 0 .. PACK_WARPS-1
    int row0 = pw * ROWS_PER_UNIT;                            // (b*D + d) index
    int b = row0 / D;
    int d = row0 - b * D;

    float4 ga[ROWS_PER_UNIT], gb[ROWS_PER_UNIT];
#pragma unroll
    for (int r = 0; r < ROWS_PER_UNIT; ++r) {
        const float4* rr = (const float4*)(lit + (size_t)(row0 + r) * L);
        ga[r] = rr[lane];                                     // l = 4*lane..+3
        gb[r] = (lane < 17) ? rr[32 + lane]                   // l = 128+4*lane..+3
                            : make_float4(0.f, 0.f, 0.f, 0.f);
    }

#pragma unroll
    for (int r = 0; r < ROWS_PER_UNIT; ++r) {
        unsigned w0 = __ballot_sync(0xFFFFFFFFu, ga[r].x > 0.5f);
        unsigned w1 = __ballot_sync(0xFFFFFFFFu, ga[r].y > 0.5f);
        unsigned w2 = __ballot_sync(0xFFFFFFFFu, ga[r].z > 0.5f);
        unsigned w3 = __ballot_sync(0xFFFFFFFFu, ga[r].w > 0.5f);
        unsigned w4 = __ballot_sync(0xFFFFFFFFu, gb[r].x > 0.5f);
        unsigned w5 = __ballot_sync(0xFFFFFFFFu, gb[r].y > 0.5f);
        unsigned w6 = __ballot_sync(0xFFFFFFFFu, gb[r].z > 0.5f);
        unsigned w7 = __ballot_sync(0xFFFFFFFFu, gb[r].w > 0.5f);

        unsigned out = w0;
        if (lane == 1) out = w1;
        if (lane == 2) out = w2;
        if (lane == 3) out = w3;
        if (lane == 4) out = w4;
        if (lane == 5) out = w5;
        if (lane == 6) out = w6;
        if (lane == 7) out = w7;
        if (lane < NWP) g_litbits[d * (B * NWP) + b * NWP + lane] = out;

        if (++d == D) { d = 0; ++b; }
    }
}

// ---------------- kernel 2: clause AND-reduce + all outputs ----------------
// One warp: clause m x 4 batches. Lanes = (bq 0..3) x (w 0..7), all active.
// Each gather LDG (32 lanes, same d) hits exactly one 128B line of g_litbits.
// Logits fused: fired clauses atomically add alpha*sign into out_logits.
__global__ void clause_kernel(const float* __restrict__ alpha,
                              float* __restrict__ out_map,
                              float* __restrict__ out_or,
                              float* __restrict__ out_logits) {
    int wblk = threadIdx.x >> 5;
    int lane = threadIdx.x & 31;
    int m  = blockIdx.x * 8 + wblk;                   // 320 x 8 = 2560
    int b0 = blockIdx.y * 4;                          // 8 x 4 = 32

    int bq = lane >> 3;                               // 0..3
    int w  = lane & 7;                                // 0..7

    int cnt4 = g_cnt[m];
    const int16_t* idxp = g_idx + m * MAXSEL;

    unsigned acc = 0xFFFFFFFFu;
    {
        const uint32_t* base = g_litbits + (b0 + bq) * NWP + w;
        for (int i = 0; i < cnt4; i += 4) {
            uint64_t q = *(const uint64_t*)(idxp + i);
            int d0 = (int)(q & 0xFFFFu);
            int d1 = (int)((q >> 16) & 0xFFFFu);
            int d2 = (int)((q >> 32) & 0xFFFFu);
            int d3 = (int)((q >> 48) & 0xFFFFu);
            unsigned a0 = base[d0 * (B * NWP)];
            unsigned a1 = base[d1 * (B * NWP)];
            unsigned a2 = base[d2 * (B * NWP)];
            unsigned a3 = base[d3 * (B * NWP)];
            acc &= (a0 & a1) & (a2 & a3);
        }
        if (w >= 4) acc &= 0x1FFFFu;                  // group-B words: 17 valid bits
    }

    // ---- clause_map stores: per batch row, 49 float4 slots ----
#pragma unroll
    for (int q = 0; q < 4; ++q) {
        uint4* row = (uint4*)(out_map + ((size_t)(b0 + q) * M + m) * L);
        unsigned w0 = __shfl_sync(0xFFFFFFFFu, acc, q * 8 + 0);
        unsigned w1 = __shfl_sync(0xFFFFFFFFu, acc, q * 8 + 1);
        unsigned w2 = __shfl_sync(0xFFFFFFFFu, acc, q * 8 + 2);
        unsigned w3 = __shfl_sync(0xFFFFFFFFu, acc, q * 8 + 3);
        uint4 v;
        v.x = ((w0 >> lane) & 1u) * 0x3F800000u;
        v.y = ((w1 >> lane) & 1u) * 0x3F800000u;
        v.z = ((w2 >> lane) & 1u) * 0x3F800000u;
        v.w = ((w3 >> lane) & 1u) * 0x3F800000u;
        row[lane] = v;
        unsigned w4 = __shfl_sync(0xFFFFFFFFu, acc, q * 8 + 4);
        unsigned w5 = __shfl_sync(0xFFFFFFFFu, acc, q * 8 + 5);
        unsigned w6 = __shfl_sync(0xFFFFFFFFu, acc, q * 8 + 6);
        unsigned w7 = __shfl_sync(0xFFFFFFFFu, acc, q * 8 + 7);
        if (lane < 17) {
            uint4 u;
            u.x = ((w4 >> lane) & 1u) * 0x3F800000u;
            u.y = ((w5 >> lane) & 1u) * 0x3F800000u;
            u.z = ((w6 >> lane) & 1u) * 0x3F800000u;
            u.w = ((w7 >> lane) & 1u) * 0x3F800000u;
            row[32 + lane] = u;
        }
    }

    // ---- clause_or + fused logits contribution ----
    bool nz = (acc != 0u);
    unsigned bal = __ballot_sync(0xFFFFFFFFu, nz);
    if (lane < 4) {
        unsigned any = (bal >> (lane * 8)) & 0xFFu;
        int b = b0 + lane;
        out_or[b * M + m] = any ? 1.0f : 0.0f;
        if (any) {
            int c = m / K;
            int k = m - c * K;
            float sg  = (k < (K / 2)) ? 1.0f : -1.0f;
            atomicAdd(out_logits + b * CC + c, alpha[m] * sg);   // REDG
        }
    }
}

// ---------------- launch ----------------
extern "C" void kernel_launch(void* const* d_in, const int* in_sizes, int n_in,
                              void* d_out, int out_size) {
    const void* p_lit   = d_in[0];
    const void* p_mask  = d_in[1];
    const void* p_alpha = d_in[2];
    for (int i = 0; i < n_in; ++i) {
        if (in_sizes[i] == B * D * L)  p_lit   = d_in[i];
        else if (in_sizes[i] == M * D) p_mask  = d_in[i];
        else if (in_sizes[i] == M)     p_alpha = d_in[i];
    }
    const float* literals = (const float*)p_lit;
    const float* alpha    = (const float*)p_alpha;

    float* out_map    = (float*)d_out;                 // [B,M,L]
    float* out_or     = out_map + (size_t)B * M * L;   // [B,M]
    float* out_logits = out_or + (size_t)B * M;        // [B,CC]

    prep_kernel<<<PREP_BLOCKS, 256>>>(literals, p_mask, out_logits);

    dim3 cgrid(M / 8, B / 4);
    clause_kernel<<<cgrid, 256>>>(alpha, out_map, out_or, out_logits);
}